// round 5
// baseline (speedup 1.0000x reference)
#include <cuda_runtime.h>
#include <math.h>
#include <stdint.h>

typedef unsigned long long ull;

// ---------------------------------------------------------------------------
// Problem dimensions
// ---------------------------------------------------------------------------
#define B_   256
#define T_   256
#define DIN  256
#define H_   1024
#define FC_  512
#define DOUT 24
#define G4   4096    // 4*H
#define KTOT 1280    // H + DIN (fused [h | x_t] contraction)

// GEMM tiling
#define BM 32
#define BN 64
#define BK 32
#define SB_LD 68                       // padded sB row stride (floats)
#define NST_G (KTOT / BK)              // 40 stages for gates
#define NST_D (H_ / BK)                // 32 stages for decomp
#define GATE_TILES ((G4 / BN) * (B_ / BM))   // 64*8 = 512
#define DEC_TILES  ((H_ / BN) * (B_ / BM))   // 16*8 = 128

// ---------------------------------------------------------------------------
// Device scratch (static globals — no allocation allowed)
// ---------------------------------------------------------------------------
static __device__ float g_gate[(size_t)B_ * G4];   // raw h@Ux + x@Wx (no bias)
static __device__ float g_dec[(size_t)B_ * H_];    // raw c@Wd (no bias)
static __device__ float g_h[2][(size_t)B_ * H_];   // ping-pong hidden
static __device__ float g_c[2][(size_t)B_ * H_];   // ping-pong cell
static __device__ float g_ball[G4];                // b_lin + b_extra
static __device__ float g_bd2[H_];                 // bd + b_decomp
static __device__ float g_tmp[(size_t)B_ * FC_];   // fc1 activation

// ---------------------------------------------------------------------------
// Packed fp32x2 helpers (Blackwell FFMA2)
// ---------------------------------------------------------------------------
__device__ __forceinline__ ull pk2(float lo, float hi) {
    ull r;
    asm("mov.b64 %0, {%1, %2};" : "=l"(r) : "f"(lo), "f"(hi));
    return r;
}
__device__ __forceinline__ void fma2(ull& d, ull a, ull b) {
    asm("fma.rn.f32x2 %0, %1, %2, %0;" : "+l"(d) : "l"(a), "l"(b));
}
__device__ __forceinline__ float2 upk(ull v) {
    float2 f;
    asm("mov.b64 {%0, %1}, %2;" : "=f"(f.x), "=f"(f.y) : "l"(v));
    return f;
}
__device__ __forceinline__ float sigm(float x) {
    return 1.0f / (1.0f + expf(-x));
}

// ---------------------------------------------------------------------------
// Init: zero initial state, prebake bias sums
// ---------------------------------------------------------------------------
__global__ __launch_bounds__(256) void init_kernel(
    const float* __restrict__ b_lin, const float* __restrict__ b_extra,
    const float* __restrict__ bd, const float* __restrict__ b_decomp)
{
    int i = blockIdx.x * 256 + threadIdx.x;    // 65536 threads
    float4 z = make_float4(0.f, 0.f, 0.f, 0.f);
    *reinterpret_cast<float4*>(&g_h[0][(size_t)i * 4]) = z;
    *reinterpret_cast<float4*>(&g_c[0][(size_t)i * 4]) = z;
    if (i < G4 / 4) {
        float4 a = *reinterpret_cast<const float4*>(&b_lin[i * 4]);
        float4 b = *reinterpret_cast<const float4*>(&b_extra[i * 4]);
        float4 r = make_float4(a.x + b.x, a.y + b.y, a.z + b.z, a.w + b.w);
        *reinterpret_cast<float4*>(&g_ball[i * 4]) = r;
    }
    if (i < H_ / 4) {
        float4 a = *reinterpret_cast<const float4*>(&bd[i * 4]);
        float4 b = *reinterpret_cast<const float4*>(&b_decomp[i * 4]);
        float4 r = make_float4(a.x + b.x, a.y + b.y, a.z + b.z, a.w + b.w);
        *reinterpret_cast<float4*>(&g_bd2[i * 4]) = r;
    }
}

// ---------------------------------------------------------------------------
// Per-step GEMM: 640 blocks.
//   blocks [0,512): gates  [32b x 64n] = [h | x_t] @ [Ux ; Wx],  K=1280
//   blocks [512,640): decomp [32b x 64n] = c @ Wd,               K=1024
// Warp layout: warp w -> rows w*4..w*4+3; lane l -> cols n0+2l, n0+2l+1.
// A stored in smem duplicated as (a,a) u64 in [m][k] order -> broadcast
// LDS.128 feeds FFMA2 directly with zero packing MOVs.
// ---------------------------------------------------------------------------
__global__ __launch_bounds__(256) void step_gemm(
    int t,
    const float* __restrict__ x,    // [B][T][DIN]
    const float* __restrict__ Ux,   // [H][4H]
    const float* __restrict__ Wx,   // [DIN][4H]
    const float* __restrict__ Wd)   // [H][H]
{
    __shared__ __align__(16) ull   sA[BM * BK];     // [m][k], dup pairs (8 KB)
    __shared__ __align__(16) float sB[BK * SB_LD];  // [k][n], padded (8.7 KB)

    const int bid = blockIdx.x;
    const bool isg = (bid < GATE_TILES);
    const int pr = t & 1;

    int n0, b0, nst, ldO;
    const float* Aroot;
    float* Out;
    if (isg) {
        n0 = (bid & 63) * BN;
        b0 = (bid >> 6) * BM;
        Aroot = g_h[pr];
        nst = NST_G;
        Out = g_gate;
        ldO = G4;
    } else {
        int d = bid - GATE_TILES;
        n0 = (d & 15) * BN;
        b0 = (d >> 4) * BM;
        Aroot = g_c[pr];
        nst = NST_D;
        Out = g_dec;
        ldO = H_;
    }

    const int tid  = threadIdx.x;
    const int lane = tid & 31;
    const int warp = tid >> 5;
    const int m0   = warp * 4;

    // staging coordinates
    const int rA = tid >> 3, qA = tid & 7;    // A: row rA, k = qA*4..qA*4+3
    const int kB = tid >> 4, qB = tid & 15;   // B: rows kB, kB+16; col n0+qB*4

    ull acc0 = 0ULL, acc1 = 0ULL, acc2 = 0ULL, acc3 = 0ULL;
    float4 fa, fb0, fb1;

    // --- prefetch stage 0 into registers ---
    {
        int kg = qA * 4;
        fa = *reinterpret_cast<const float4*>(&Aroot[(size_t)(b0 + rA) * H_ + kg]);
        if (isg) {
            fb0 = *reinterpret_cast<const float4*>(&Ux[(size_t)kB * G4 + n0 + qB * 4]);
            fb1 = *reinterpret_cast<const float4*>(&Ux[(size_t)(kB + 16) * G4 + n0 + qB * 4]);
        } else {
            fb0 = *reinterpret_cast<const float4*>(&Wd[(size_t)kB * H_ + n0 + qB * 4]);
            fb1 = *reinterpret_cast<const float4*>(&Wd[(size_t)(kB + 16) * H_ + n0 + qB * 4]);
        }
    }

    for (int s = 0; ; s++) {
        // --- store prefetched stage to smem (A duplicated) ---
        ulonglong2 d0, d1;
        d0.x = pk2(fa.x, fa.x); d0.y = pk2(fa.y, fa.y);
        d1.x = pk2(fa.z, fa.z); d1.y = pk2(fa.w, fa.w);
        *reinterpret_cast<ulonglong2*>(&sA[rA * BK + qA * 4])     = d0;
        *reinterpret_cast<ulonglong2*>(&sA[rA * BK + qA * 4 + 2]) = d1;
        *reinterpret_cast<float4*>(&sB[kB * SB_LD + qB * 4])        = fb0;
        *reinterpret_cast<float4*>(&sB[(kB + 16) * SB_LD + qB * 4]) = fb1;
        __syncthreads();

        const bool last = (s == nst - 1);
        if (!last) {
            // --- prefetch stage s+1 (global latency hidden by compute) ---
            int k0 = (s + 1) * BK;
            int kgA = k0 + qA * 4;
            if (isg && kgA >= H_) {
                fa = *reinterpret_cast<const float4*>(
                    &x[((size_t)(b0 + rA) * T_ + t) * DIN + (kgA - H_)]);
            } else {
                fa = *reinterpret_cast<const float4*>(
                    &Aroot[(size_t)(b0 + rA) * H_ + kgA]);
            }
            int kg0 = k0 + kB, kg1 = k0 + kB + 16;
            if (isg) {
                fb0 = (kg0 < H_)
                    ? *reinterpret_cast<const float4*>(&Ux[(size_t)kg0 * G4 + n0 + qB * 4])
                    : *reinterpret_cast<const float4*>(&Wx[(size_t)(kg0 - H_) * G4 + n0 + qB * 4]);
                fb1 = (kg1 < H_)
                    ? *reinterpret_cast<const float4*>(&Ux[(size_t)kg1 * G4 + n0 + qB * 4])
                    : *reinterpret_cast<const float4*>(&Wx[(size_t)(kg1 - H_) * G4 + n0 + qB * 4]);
            } else {
                fb0 = *reinterpret_cast<const float4*>(&Wd[(size_t)kg0 * H_ + n0 + qB * 4]);
                fb1 = *reinterpret_cast<const float4*>(&Wd[(size_t)kg1 * H_ + n0 + qB * 4]);
            }
        }

        // --- compute 32 k from smem: broadcast A (dup), lane-sliced B ---
#pragma unroll
        for (int kp = 0; kp < BK / 2; kp++) {
            ull bv0 = *reinterpret_cast<const ull*>(&sB[(2 * kp) * SB_LD + 2 * lane]);
            ull bv1 = *reinterpret_cast<const ull*>(&sB[(2 * kp + 1) * SB_LD + 2 * lane]);
            ulonglong2 a0 = *reinterpret_cast<const ulonglong2*>(&sA[(m0 + 0) * BK + 2 * kp]);
            ulonglong2 a1 = *reinterpret_cast<const ulonglong2*>(&sA[(m0 + 1) * BK + 2 * kp]);
            ulonglong2 a2 = *reinterpret_cast<const ulonglong2*>(&sA[(m0 + 2) * BK + 2 * kp]);
            ulonglong2 a3 = *reinterpret_cast<const ulonglong2*>(&sA[(m0 + 3) * BK + 2 * kp]);
            fma2(acc0, a0.x, bv0); fma2(acc0, a0.y, bv1);
            fma2(acc1, a1.x, bv0); fma2(acc1, a1.y, bv1);
            fma2(acc2, a2.x, bv0); fma2(acc2, a2.y, bv1);
            fma2(acc3, a3.x, bv0); fma2(acc3, a3.y, bv1);
        }
        if (last) break;
        __syncthreads();
    }

    // --- write raw GEMM results (bias/activation applied in epilogue) ---
    const int n = n0 + 2 * lane;
    float2 v;
    v = upk(acc0); *reinterpret_cast<float2*>(&Out[(size_t)(b0 + m0 + 0) * ldO + n]) = v;
    v = upk(acc1); *reinterpret_cast<float2*>(&Out[(size_t)(b0 + m0 + 1) * ldO + n]) = v;
    v = upk(acc2); *reinterpret_cast<float2*>(&Out[(size_t)(b0 + m0 + 2) * ldO + n]) = v;
    v = upk(acc3); *reinterpret_cast<float2*>(&Out[(size_t)(b0 + m0 + 3) * ldO + n]) = v;
}

// ---------------------------------------------------------------------------
// Per-step epilogue: time-decay decomposition + LSTM gate math.
// 65536 threads x float4 over the 256x1024 state.
// ---------------------------------------------------------------------------
__global__ __launch_bounds__(256) void step_epi(
    int t, const float* __restrict__ elapsed)   // [B][T]
{
    int idx = blockIdx.x * 256 + threadIdx.x;   // 0..65535
    int b = idx >> 8;
    int n4 = (idx & 255) << 2;

    const int pr = t & 1;
    const float* c_in = g_c[pr];
    float* c_out = g_c[1 - pr];
    float* h_out = g_h[1 - pr];

    float dt = elapsed[(size_t)b * T_ + t];
    float Td = 1.0f / logf(dt + 2.7183f);

    float4 dec = *reinterpret_cast<const float4*>(&g_dec[(size_t)b * H_ + n4]);
    float4 bb  = *reinterpret_cast<const float4*>(&g_bd2[n4]);
    float4 cp  = *reinterpret_cast<const float4*>(&c_in[(size_t)b * H_ + n4]);
    const float* grow = &g_gate[(size_t)b * G4];
    float4 gi = *reinterpret_cast<const float4*>(&grow[0 * H_ + n4]);
    float4 gf = *reinterpret_cast<const float4*>(&grow[1 * H_ + n4]);
    float4 go = *reinterpret_cast<const float4*>(&grow[2 * H_ + n4]);
    float4 gc = *reinterpret_cast<const float4*>(&grow[3 * H_ + n4]);
    float4 bi = *reinterpret_cast<const float4*>(&g_ball[0 * H_ + n4]);
    float4 bf = *reinterpret_cast<const float4*>(&g_ball[1 * H_ + n4]);
    float4 bo = *reinterpret_cast<const float4*>(&g_ball[2 * H_ + n4]);
    float4 bc = *reinterpret_cast<const float4*>(&g_ball[3 * H_ + n4]);

    float4 cn, hn;
#define TLSTM_COMP(X)                                                     \
    {                                                                     \
        float cst = tanhf(dec.X + bb.X);                                  \
        float cm = cp.X - cst + Td * cst;                                 \
        float c2 = sigm(gf.X + bf.X) * cm +                               \
                   sigm(gi.X + bi.X) * tanhf(gc.X + bc.X);                \
        cn.X = c2;                                                        \
        hn.X = sigm(go.X + bo.X) * tanhf(c2);                             \
    }
    TLSTM_COMP(x) TLSTM_COMP(y) TLSTM_COMP(z) TLSTM_COMP(w)
#undef TLSTM_COMP

    *reinterpret_cast<float4*>(&c_out[(size_t)b * H_ + n4]) = cn;
    *reinterpret_cast<float4*>(&h_out[(size_t)b * H_ + n4]) = hn;
}

// ---------------------------------------------------------------------------
// Output head
// ---------------------------------------------------------------------------
__global__ __launch_bounds__(256) void fc1_kernel(
    const float* __restrict__ w,     // [H][FC]
    const float* __restrict__ bias)  // [FC]
{
    int idx = blockIdx.x * 256 + threadIdx.x;  // B*FC = 131072
    int b = idx >> 9, n = idx & 511;
    const float* hrow = &g_h[0][(size_t)b * H_];
    float acc = bias[n];
#pragma unroll 8
    for (int k = 0; k < H_; k++)
        acc += hrow[k] * w[(size_t)k * FC_ + n];
    g_tmp[idx] = fmaxf(acc, 0.0f);
}

__global__ __launch_bounds__(256) void fco_kernel(
    const float* __restrict__ w,      // [FC][DOUT]
    const float* __restrict__ bias,   // [DOUT]
    float* __restrict__ out)          // [B][DOUT]
{
    int idx = blockIdx.x * 256 + threadIdx.x;  // B*DOUT = 6144
    if (idx >= B_ * DOUT) return;
    int b = idx / DOUT, n = idx % DOUT;
    const float* trow = &g_tmp[(size_t)b * FC_];
    float acc = bias[n];
#pragma unroll 8
    for (int k = 0; k < FC_; k++)
        acc += trow[k] * w[(size_t)k * DOUT + n];
    out[idx] = acc;
}

// ---------------------------------------------------------------------------
// Launch
// ---------------------------------------------------------------------------
extern "C" void kernel_launch(void* const* d_in, const int* in_sizes, int n_in,
                              void* d_out, int out_size) {
    (void)in_sizes; (void)n_in; (void)out_size;
    const float* x        = (const float*)d_in[0];
    const float* elapsed  = (const float*)d_in[1];
    const float* Wx       = (const float*)d_in[2];
    const float* Ux       = (const float*)d_in[3];
    const float* b_lin    = (const float*)d_in[4];
    const float* b_extra  = (const float*)d_in[5];
    const float* Wd       = (const float*)d_in[6];
    const float* bd       = (const float*)d_in[7];
    const float* b_decomp = (const float*)d_in[8];
    const float* fc1_w    = (const float*)d_in[9];
    const float* fc1_b    = (const float*)d_in[10];
    const float* fco_w    = (const float*)d_in[11];
    const float* fco_b    = (const float*)d_in[12];
    float* out = (float*)d_out;

    // zero initial state + prebake bias sums
    init_kernel<<<256, 256>>>(b_lin, b_extra, bd, b_decomp);

    // sequential recurrence: per step, one fused GEMM (x@Wx folded in via
    // K=1280 contraction) + one elementwise epilogue
    for (int t = 0; t < T_; t++) {
        step_gemm<<<GATE_TILES + DEC_TILES, 256>>>(t, x, Ux, Wx, Wd);
        step_epi<<<256, 256>>>(t, elapsed);
    }

    // output head on final hidden state (in g_h[0] after t=255)
    fc1_kernel<<<(B_ * FC_) / 256, 256>>>(fc1_w, fc1_b);
    fco_kernel<<<(B_ * DOUT + 255) / 256, 256>>>(fco_w, fco_b, out);
}

// round 6
// speedup vs baseline: 1.2422x; 1.2422x over previous
#include <cuda_runtime.h>
#include <math.h>
#include <stdint.h>

typedef unsigned long long ull;

// ---------------------------------------------------------------------------
// Problem dimensions
// ---------------------------------------------------------------------------
#define B_   256
#define T_   256
#define DIN  256
#define H_   1024
#define FC_  512
#define DOUT 24
#define G4   4096      // 4*H
#define KTOT 1280      // H + DIN (fused [h | x_t] contraction)

// GEMM tiling
#define BM 64
#define BN 128
#define BK 16
#define SA_LD 66                   // u64 stride per k-row of sA (padded)
#define SK 4                       // split-K factor
#define KSG (KTOT / SK)            // 320  -> 20 stages
#define KSD (H_ / SK)              // 256  -> 16 stages
#define NSTG (KSG / BK)
#define NSTD (KSD / BK)
#define GTILES (4 * 32 * SK)       // (256/64)*(4096/128)*SK = 512
#define DTILES (4 * 8 * SK)        // (256/64)*(1024/128)*SK = 128

// ---------------------------------------------------------------------------
// Device scratch (static globals — no allocation allowed)
// ---------------------------------------------------------------------------
static __device__ float g_gateP[SK][(size_t)B_ * G4];  // split-K partials, gates
static __device__ float g_decP[SK][(size_t)B_ * H_];   // split-K partials, decomp
static __device__ float g_h[2][(size_t)B_ * H_];       // ping-pong hidden
static __device__ float g_c[2][(size_t)B_ * H_];       // ping-pong cell
static __device__ float g_ball[G4];                    // b_lin + b_extra
static __device__ float g_bd2[H_];                     // bd + b_decomp
static __device__ float g_tmp[(size_t)B_ * FC_];       // fc1 activation

// ---------------------------------------------------------------------------
// Packed fp32x2 helpers (Blackwell FFMA2)
// ---------------------------------------------------------------------------
__device__ __forceinline__ ull pk2(float lo, float hi) {
    ull r;
    asm("mov.b64 %0, {%1, %2};" : "=l"(r) : "f"(lo), "f"(hi));
    return r;
}
__device__ __forceinline__ void fma2(ull& d, ull a, ull b) {
    asm("fma.rn.f32x2 %0, %1, %2, %0;" : "+l"(d) : "l"(a), "l"(b));
}
__device__ __forceinline__ float2 upk(ull v) {
    float2 f;
    asm("mov.b64 {%0, %1}, %2;" : "=f"(f.x), "=f"(f.y) : "l"(v));
    return f;
}
__device__ __forceinline__ float sigm(float x) {
    return 1.0f / (1.0f + expf(-x));
}

// ---------------------------------------------------------------------------
// Init: zero initial state, prebake bias sums
// ---------------------------------------------------------------------------
__global__ __launch_bounds__(256) void init_kernel(
    const float* __restrict__ b_lin, const float* __restrict__ b_extra,
    const float* __restrict__ bd, const float* __restrict__ b_decomp)
{
    int i = blockIdx.x * 256 + threadIdx.x;    // 65536 threads
    float4 z = make_float4(0.f, 0.f, 0.f, 0.f);
    *reinterpret_cast<float4*>(&g_h[0][(size_t)i * 4]) = z;
    *reinterpret_cast<float4*>(&g_c[0][(size_t)i * 4]) = z;
    if (i < G4 / 4) {
        float4 a = *reinterpret_cast<const float4*>(&b_lin[i * 4]);
        float4 b = *reinterpret_cast<const float4*>(&b_extra[i * 4]);
        *reinterpret_cast<float4*>(&g_ball[i * 4]) =
            make_float4(a.x + b.x, a.y + b.y, a.z + b.z, a.w + b.w);
    }
    if (i < H_ / 4) {
        float4 a = *reinterpret_cast<const float4*>(&bd[i * 4]);
        float4 b = *reinterpret_cast<const float4*>(&b_decomp[i * 4]);
        *reinterpret_cast<float4*>(&g_bd2[i * 4]) =
            make_float4(a.x + b.x, a.y + b.y, a.z + b.z, a.w + b.w);
    }
}

// ---------------------------------------------------------------------------
// Per-step GEMM (split-K=4, 640 blocks):
//   blocks [0,512):   gates  [64b x 128n] partial = [h | x_t] @ [Ux ; Wx]
//   blocks [512,640): decomp [64b x 128n] partial = c @ Wd
// Thread tile 4m x 8n via FFMA2. A held in smem pre-duplicated as (a,a)
// u64 pairs in [k][m] order -> broadcast LDS.128, zero packing MOVs.
// Double-buffered smem, one __syncthreads per stage, register prefetch.
// ---------------------------------------------------------------------------
__global__ __launch_bounds__(256, 2) void step_gemm(
    int t,
    const float* __restrict__ x,    // [B][T][DIN]
    const float* __restrict__ Ux,   // [H][4H]
    const float* __restrict__ Wx,   // [DIN][4H]
    const float* __restrict__ Wd)   // [H][H]
{
    __shared__ __align__(16) ull   sA[2][BK * SA_LD];  // 16.5 KB
    __shared__ __align__(16) float sB[2][BK * BN];     // 16 KB

    const int bid = blockIdx.x;
    const bool isg = (bid < GTILES);
    const int pr = t & 1;

    int n0, b0, ks, nst, ldO;
    const float* Aroot;
    float* Out;
    if (isg) {
        int r = bid;
        ks = r & (SK - 1); r >>= 2;
        n0 = (r & 31) * BN;            // 32 n-tiles
        b0 = (r >> 5) * BM;            // 4 m-tiles
        Aroot = g_h[pr];
        nst = NSTG; ldO = G4;
        Out = &g_gateP[ks][0];
    } else {
        int r = bid - GTILES;
        ks = r & (SK - 1); r >>= 2;
        n0 = (r & 7) * BN;             // 8 n-tiles
        b0 = (r >> 3) * BM;            // 4 m-tiles
        Aroot = g_c[pr];
        nst = NSTD; ldO = H_;
        Out = &g_decP[ks][0];
    }
    const int koff = ks * (isg ? KSG : KSD);

    const int tid  = threadIdx.x;
    const int tn   = tid & 15;     // 8 n-cols each
    const int tm   = tid >> 4;     // 4 m-rows each

    // staging coordinates
    const int rA = tid >> 2, qA = tid & 3;     // A: row rA, k-quad qA
    const int kB = tid >> 4, qB = tid & 15;    // B: k-row kB, col-quad qB

    ull acc[4][4];
#pragma unroll
    for (int i = 0; i < 4; i++)
#pragma unroll
        for (int p = 0; p < 4; p++) acc[i][p] = 0ULL;

    float4 fa, fb0, fb1;

    // ---- register prefetch of one stage ----
    auto prefetch = [&](int s) {
        int k0 = koff + s * BK;
        int kgA = k0 + qA * 4;
        if (isg && kgA >= H_) {
            fa = *reinterpret_cast<const float4*>(
                &x[((size_t)(b0 + rA) * T_ + t) * DIN + (kgA - H_)]);
        } else {
            fa = *reinterpret_cast<const float4*>(
                &Aroot[(size_t)(b0 + rA) * H_ + kgA]);
        }
        int kg = k0 + kB;
        if (isg) {
            const float* Brow = (kg < H_) ? &Ux[(size_t)kg * G4]
                                          : &Wx[(size_t)(kg - H_) * G4];
            fb0 = *reinterpret_cast<const float4*>(&Brow[n0 + qB * 4]);
            fb1 = *reinterpret_cast<const float4*>(&Brow[n0 + 64 + qB * 4]);
        } else {
            const float* Brow = &Wd[(size_t)kg * H_];
            fb0 = *reinterpret_cast<const float4*>(&Brow[n0 + qB * 4]);
            fb1 = *reinterpret_cast<const float4*>(&Brow[n0 + 64 + qB * 4]);
        }
    };
    auto store_stage = [&](int buf) {
        ull* a = sA[buf];
        a[(qA * 4 + 0) * SA_LD + rA] = pk2(fa.x, fa.x);
        a[(qA * 4 + 1) * SA_LD + rA] = pk2(fa.y, fa.y);
        a[(qA * 4 + 2) * SA_LD + rA] = pk2(fa.z, fa.z);
        a[(qA * 4 + 3) * SA_LD + rA] = pk2(fa.w, fa.w);
        *reinterpret_cast<float4*>(&sB[buf][kB * BN + qB * 4])      = fb0;
        *reinterpret_cast<float4*>(&sB[buf][kB * BN + 64 + qB * 4]) = fb1;
    };

    prefetch(0);
    store_stage(0);
    __syncthreads();

    for (int s = 0; ; s++) {
        const int buf = s & 1;
        const bool last = (s == nst - 1);
        if (!last) prefetch(s + 1);

        // ---- compute 16 k from smem ----
#pragma unroll
        for (int k = 0; k < BK; k++) {
            const ulonglong2* ap =
                reinterpret_cast<const ulonglong2*>(&sA[buf][k * SA_LD + tm * 4]);
            ulonglong2 a01 = ap[0];          // rows tm*4, tm*4+1 (dup pairs)
            ulonglong2 a23 = ap[1];          // rows tm*4+2, tm*4+3
            const ulonglong2* bp =
                reinterpret_cast<const ulonglong2*>(&sB[buf][k * BN + tn * 8]);
            ulonglong2 b01 = bp[0];          // n pairs 0,1
            ulonglong2 b23 = bp[1];          // n pairs 2,3
            fma2(acc[0][0], a01.x, b01.x); fma2(acc[0][1], a01.x, b01.y);
            fma2(acc[0][2], a01.x, b23.x); fma2(acc[0][3], a01.x, b23.y);
            fma2(acc[1][0], a01.y, b01.x); fma2(acc[1][1], a01.y, b01.y);
            fma2(acc[1][2], a01.y, b23.x); fma2(acc[1][3], a01.y, b23.y);
            fma2(acc[2][0], a23.x, b01.x); fma2(acc[2][1], a23.x, b01.y);
            fma2(acc[2][2], a23.x, b23.x); fma2(acc[2][3], a23.x, b23.y);
            fma2(acc[3][0], a23.y, b01.x); fma2(acc[3][1], a23.y, b01.y);
            fma2(acc[3][2], a23.y, b23.x); fma2(acc[3][3], a23.y, b23.y);
        }
        if (last) break;
        // buf^1 was fully consumed before the sync that ended iteration s-1,
        // so overwriting it here is safe with a single sync per stage.
        store_stage(buf ^ 1);
        __syncthreads();
    }

    // ---- write partial tile ----
    const int n = n0 + tn * 8;
#pragma unroll
    for (int i = 0; i < 4; i++) {
        float2 v0 = upk(acc[i][0]), v1 = upk(acc[i][1]);
        float2 v2 = upk(acc[i][2]), v3 = upk(acc[i][3]);
        float* orow = &Out[(size_t)(b0 + tm * 4 + i) * ldO + n];
        *reinterpret_cast<float4*>(&orow[0]) = make_float4(v0.x, v0.y, v1.x, v1.y);
        *reinterpret_cast<float4*>(&orow[4]) = make_float4(v2.x, v2.y, v3.x, v3.y);
    }
}

// ---------------------------------------------------------------------------
// Per-step epilogue: sum split-K partials, time-decay decomposition,
// LSTM gate math. 65536 threads x float4.
// ---------------------------------------------------------------------------
__global__ __launch_bounds__(256) void step_epi(
    int t, const float* __restrict__ elapsed)   // [B][T]
{
    int idx = blockIdx.x * 256 + threadIdx.x;   // 0..65535
    int b = idx >> 8;
    int n4 = (idx & 255) << 2;

    const int pr = t & 1;
    const float* c_in = g_c[pr];
    float* c_out = g_c[1 - pr];
    float* h_out = g_h[1 - pr];

    float dt = elapsed[(size_t)b * T_ + t];
    float Td = 1.0f / logf(dt + 2.7183f);

    float4 dec = make_float4(0.f, 0.f, 0.f, 0.f);
    float4 gi = dec, gf = dec, go = dec, gc = dec;
#pragma unroll
    for (int s = 0; s < SK; s++) {
        float4 d = *reinterpret_cast<const float4*>(&g_decP[s][(size_t)b * H_ + n4]);
        dec.x += d.x; dec.y += d.y; dec.z += d.z; dec.w += d.w;
        const float* grow = &g_gateP[s][(size_t)b * G4];
        float4 a;
        a = *reinterpret_cast<const float4*>(&grow[0 * H_ + n4]);
        gi.x += a.x; gi.y += a.y; gi.z += a.z; gi.w += a.w;
        a = *reinterpret_cast<const float4*>(&grow[1 * H_ + n4]);
        gf.x += a.x; gf.y += a.y; gf.z += a.z; gf.w += a.w;
        a = *reinterpret_cast<const float4*>(&grow[2 * H_ + n4]);
        go.x += a.x; go.y += a.y; go.z += a.z; go.w += a.w;
        a = *reinterpret_cast<const float4*>(&grow[3 * H_ + n4]);
        gc.x += a.x; gc.y += a.y; gc.z += a.z; gc.w += a.w;
    }

    float4 bb  = *reinterpret_cast<const float4*>(&g_bd2[n4]);
    float4 cp  = *reinterpret_cast<const float4*>(&c_in[(size_t)b * H_ + n4]);
    float4 bi = *reinterpret_cast<const float4*>(&g_ball[0 * H_ + n4]);
    float4 bf = *reinterpret_cast<const float4*>(&g_ball[1 * H_ + n4]);
    float4 bo = *reinterpret_cast<const float4*>(&g_ball[2 * H_ + n4]);
    float4 bc = *reinterpret_cast<const float4*>(&g_ball[3 * H_ + n4]);

    float4 cn, hn;
#define TLSTM_COMP(X)                                                     \
    {                                                                     \
        float cst = tanhf(dec.X + bb.X);                                  \
        float cm = cp.X - cst + Td * cst;                                 \
        float c2 = sigm(gf.X + bf.X) * cm +                               \
                   sigm(gi.X + bi.X) * tanhf(gc.X + bc.X);                \
        cn.X = c2;                                                        \
        hn.X = sigm(go.X + bo.X) * tanhf(c2);                             \
    }
    TLSTM_COMP(x) TLSTM_COMP(y) TLSTM_COMP(z) TLSTM_COMP(w)
#undef TLSTM_COMP

    *reinterpret_cast<float4*>(&c_out[(size_t)b * H_ + n4]) = cn;
    *reinterpret_cast<float4*>(&h_out[(size_t)b * H_ + n4]) = hn;
}

// ---------------------------------------------------------------------------
// Output head
// ---------------------------------------------------------------------------
__global__ __launch_bounds__(256) void fc1_kernel(
    const float* __restrict__ w,     // [H][FC]
    const float* __restrict__ bias)  // [FC]
{
    int idx = blockIdx.x * 256 + threadIdx.x;  // B*FC = 131072
    int b = idx >> 9, n = idx & 511;
    const float* hrow = &g_h[0][(size_t)b * H_];
    float acc = bias[n];
#pragma unroll 8
    for (int k = 0; k < H_; k++)
        acc += hrow[k] * w[(size_t)k * FC_ + n];
    g_tmp[idx] = fmaxf(acc, 0.0f);
}

__global__ __launch_bounds__(256) void fco_kernel(
    const float* __restrict__ w,      // [FC][DOUT]
    const float* __restrict__ bias,   // [DOUT]
    float* __restrict__ out)          // [B][DOUT]
{
    int idx = blockIdx.x * 256 + threadIdx.x;  // B*DOUT = 6144
    if (idx >= B_ * DOUT) return;
    int b = idx / DOUT, n = idx % DOUT;
    const float* trow = &g_tmp[(size_t)b * FC_];
    float acc = bias[n];
#pragma unroll 8
    for (int k = 0; k < FC_; k++)
        acc += trow[k] * w[(size_t)k * DOUT + n];
    out[idx] = acc;
}

// ---------------------------------------------------------------------------
// Launch
// ---------------------------------------------------------------------------
extern "C" void kernel_launch(void* const* d_in, const int* in_sizes, int n_in,
                              void* d_out, int out_size) {
    (void)in_sizes; (void)n_in; (void)out_size;
    const float* x        = (const float*)d_in[0];
    const float* elapsed  = (const float*)d_in[1];
    const float* Wx       = (const float*)d_in[2];
    const float* Ux       = (const float*)d_in[3];
    const float* b_lin    = (const float*)d_in[4];
    const float* b_extra  = (const float*)d_in[5];
    const float* Wd       = (const float*)d_in[6];
    const float* bd       = (const float*)d_in[7];
    const float* b_decomp = (const float*)d_in[8];
    const float* fc1_w    = (const float*)d_in[9];
    const float* fc1_b    = (const float*)d_in[10];
    const float* fco_w    = (const float*)d_in[11];
    const float* fco_b    = (const float*)d_in[12];
    float* out = (float*)d_out;

    // zero initial state + prebake bias sums
    init_kernel<<<256, 256>>>(b_lin, b_extra, bd, b_decomp);

    // sequential recurrence: per step, one fused split-K GEMM + one epilogue
    for (int t = 0; t < T_; t++) {
        step_gemm<<<GTILES + DTILES, 256>>>(t, x, Ux, Wx, Wd);
        step_epi<<<256, 256>>>(t, elapsed);
    }

    // output head on final hidden state (in g_h[0] after t=255)
    fc1_kernel<<<(B_ * FC_) / 256, 256>>>(fc1_w, fc1_b);
    fco_kernel<<<(B_ * DOUT + 255) / 256, 256>>>(fco_w, fco_b, out);
}

// round 7
// speedup vs baseline: 2.0130x; 1.6205x over previous
#include <cuda_runtime.h>
#include <math.h>
#include <stdint.h>

typedef unsigned long long ull;

// ---------------------------------------------------------------------------
// Problem dimensions
// ---------------------------------------------------------------------------
#define B_   256
#define T_   256
#define DIN  256
#define H_   1024
#define FC_  512
#define DOUT 24
#define G4   4096      // 4*H
#define KTOT 1280      // H + DIN (fused [h | x_t] contraction)

// GEMM tiling
#define BM 64
#define BN 128
#define BK 16
#define SA_LD 68                   // padded float stride per k-row of sA
#define SK 4                       // split-K factor
#define KSG (KTOT / SK)            // 320 -> 20 stages
#define KSD (H_ / SK)              // 256 -> 16 stages
#define NSTG (KSG / BK)
#define NSTD (KSD / BK)
#define GTILES (4 * 32 * SK)       // 512
#define DTILES (4 * 8 * SK)        // 128

// ---------------------------------------------------------------------------
// Device scratch (static globals — no allocation allowed)
// ---------------------------------------------------------------------------
static __device__ float g_gateP[SK][(size_t)B_ * G4];  // split-K partials, gates
static __device__ float g_decP[SK][(size_t)B_ * H_];   // split-K partials, decomp
static __device__ float g_h[2][(size_t)B_ * H_];       // ping-pong hidden
static __device__ float g_c[2][(size_t)B_ * H_];       // ping-pong cell
static __device__ float g_ball[G4];                    // b_lin + b_extra
static __device__ float g_bd2[H_];                     // bd + b_decomp
static __device__ float g_tmp[(size_t)B_ * FC_];       // fc1 activation

// ---------------------------------------------------------------------------
// Packed fp32x2 + cp.async helpers
// ---------------------------------------------------------------------------
__device__ __forceinline__ ull pk2(float lo, float hi) {
    ull r;
    asm("mov.b64 %0, {%1, %2};" : "=l"(r) : "f"(lo), "f"(hi));
    return r;
}
__device__ __forceinline__ void fma2(ull& d, ull a, ull b) {
    asm("fma.rn.f32x2 %0, %1, %2, %0;" : "+l"(d) : "l"(a), "l"(b));
}
__device__ __forceinline__ float2 upk(ull v) {
    float2 f;
    asm("mov.b64 {%0, %1}, %2;" : "=f"(f.x), "=f"(f.y) : "l"(v));
    return f;
}
__device__ __forceinline__ float sigm(float x) {
    return 1.0f / (1.0f + expf(-x));
}
__device__ __forceinline__ void cp16(unsigned dst, const void* src) {
    asm volatile("cp.async.cg.shared.global [%0], [%1], 16;"
                 :: "r"(dst), "l"(src));
}
#define CP_COMMIT() asm volatile("cp.async.commit_group;")
#define CP_WAIT1()  asm volatile("cp.async.wait_group 1;")
#define CP_WAIT0()  asm volatile("cp.async.wait_group 0;")

// ---------------------------------------------------------------------------
// Init: zero initial state, prebake bias sums
// ---------------------------------------------------------------------------
__global__ __launch_bounds__(256) void init_kernel(
    const float* __restrict__ b_lin, const float* __restrict__ b_extra,
    const float* __restrict__ bd, const float* __restrict__ b_decomp)
{
    int i = blockIdx.x * 256 + threadIdx.x;    // 65536 threads
    float4 z = make_float4(0.f, 0.f, 0.f, 0.f);
    *reinterpret_cast<float4*>(&g_h[0][(size_t)i * 4]) = z;
    *reinterpret_cast<float4*>(&g_c[0][(size_t)i * 4]) = z;
    if (i < G4 / 4) {
        float4 a = *reinterpret_cast<const float4*>(&b_lin[i * 4]);
        float4 b = *reinterpret_cast<const float4*>(&b_extra[i * 4]);
        *reinterpret_cast<float4*>(&g_ball[i * 4]) =
            make_float4(a.x + b.x, a.y + b.y, a.z + b.z, a.w + b.w);
    }
    if (i < H_ / 4) {
        float4 a = *reinterpret_cast<const float4*>(&bd[i * 4]);
        float4 b = *reinterpret_cast<const float4*>(&b_decomp[i * 4]);
        *reinterpret_cast<float4*>(&g_bd2[i * 4]) =
            make_float4(a.x + b.x, a.y + b.y, a.z + b.z, a.w + b.w);
    }
}

// ---------------------------------------------------------------------------
// Per-step GEMM (split-K=4, 640 blocks of 256 threads):
//   blocks [0,512):   gates  [64b x 128n] partial = [h | x_t] @ [Ux ; Wx]
//   blocks [512,640): decomp [64b x 128n] partial = c @ Wd
//
// B held in smem with a chunk permutation: each k-row's 32 16B-chunks are
// stored [even chunks | odd chunks], so compute LDS.128s are conflict-free
// (16 lanes hit 16 consecutive 16B chunks). B staged by cp.async.cg
// (L1-bypass) into a 3-buffer ring. A stored plain [k][m] (broadcast
// LDS.128 in compute; pk2 MOVs build the FFMA2 dup operand on alu pipe).
// ---------------------------------------------------------------------------
__global__ __launch_bounds__(256, 2) void step_gemm(
    int t,
    const float* __restrict__ x,    // [B][T][DIN]
    const float* __restrict__ Ux,   // [H][4H]
    const float* __restrict__ Wx,   // [DIN][4H]
    const float* __restrict__ Wd)   // [H][H]
{
    __shared__ __align__(16) float sA[2][BK * SA_LD];  // plain A, 8.5 KB
    __shared__ __align__(16) float sB[3][BK * BN];     // permuted B, 24 KB

    const int bid = blockIdx.x;
    const bool isg = (bid < GTILES);
    const int pr = t & 1;

    int n0, b0, ks, nst, ldO;
    const float* Aroot;
    float* Out;
    if (isg) {
        int r = bid;
        ks = r & (SK - 1); r >>= 2;
        n0 = (r & 31) * BN;
        b0 = (r >> 5) * BM;
        Aroot = g_h[pr];
        nst = NSTG; ldO = G4;
        Out = &g_gateP[ks][0];
    } else {
        int r = bid - GTILES;
        ks = r & (SK - 1); r >>= 2;
        n0 = (r & 7) * BN;
        b0 = (r >> 3) * BM;
        Aroot = g_c[pr];
        nst = NSTD; ldO = H_;
        Out = &g_decP[ks][0];
    }
    const int koff = ks * (isg ? KSG : KSD);

    const int tid = threadIdx.x;
    const int tn  = tid & 15;      // 8 n-cols each
    const int tm  = tid >> 4;      // 4 m-rows each

    // staging coordinates
    const int rA = tid >> 2, qA = tid & 3;    // A: row rA, k-quad qA
    const int kB = tid >> 4, qB = tid & 15;   // B: k-row kB, chunk qB

    // permuted slot offsets (in floats) for B chunks qB and 16+qB
    const int slot0 = ((qB & 1) * 16 + (qB >> 1)) * 4;
    const int slot1 = ((qB & 1) * 16 + 8 + (qB >> 1)) * 4;

    ull acc[4][4];
#pragma unroll
    for (int i = 0; i < 4; i++)
#pragma unroll
        for (int p = 0; p < 4; p++) acc[i][p] = 0ULL;

    float4 fa;

    // ---- cp.async stage of B (both 64-col halves) into ring buffer ----
    auto cpB = [&](int s) {
        int kg = koff + s * BK + kB;
        const float* Brow;
        if (isg) {
            Brow = (kg < H_) ? &Ux[(size_t)kg * G4 + n0]
                             : &Wx[(size_t)(kg - H_) * G4 + n0];
        } else {
            Brow = &Wd[(size_t)kg * H_ + n0];
        }
        float* dst = sB[s % 3] + kB * BN;
        cp16((unsigned)__cvta_generic_to_shared(dst + slot0), Brow + qB * 4);
        cp16((unsigned)__cvta_generic_to_shared(dst + slot1), Brow + 64 + qB * 4);
    };
    // ---- register prefetch of A quad ----
    auto prefA = [&](int s) {
        int kgA = koff + s * BK + qA * 4;
        if (isg && kgA >= H_) {
            fa = *reinterpret_cast<const float4*>(
                &x[((size_t)(b0 + rA) * T_ + t) * DIN + (kgA - H_)]);
        } else {
            fa = *reinterpret_cast<const float4*>(
                &Aroot[(size_t)(b0 + rA) * H_ + kgA]);
        }
    };
    auto storeA = [&](int buf) {
        float* a = sA[buf];
        a[(qA * 4 + 0) * SA_LD + rA] = fa.x;
        a[(qA * 4 + 1) * SA_LD + rA] = fa.y;
        a[(qA * 4 + 2) * SA_LD + rA] = fa.z;
        a[(qA * 4 + 3) * SA_LD + rA] = fa.w;
    };

    // ---- prologue ----
    cpB(0); CP_COMMIT();
    prefA(0);
    cpB(1); CP_COMMIT();
    storeA(0);
    prefA(1);
    CP_WAIT1();
    __syncthreads();

    for (int s = 0; ; s++) {
        // ---- compute 16 k from smem ----
        const float* abase = sA[s & 1];
        const float* bbase = sB[s % 3];
#pragma unroll
        for (int k = 0; k < BK; k++) {
            float4 av = *reinterpret_cast<const float4*>(
                &abase[k * SA_LD + tm * 4]);
            ulonglong2 b01 = *reinterpret_cast<const ulonglong2*>(
                &bbase[k * BN + tn * 4]);
            ulonglong2 b23 = *reinterpret_cast<const ulonglong2*>(
                &bbase[k * BN + 64 + tn * 4]);
            ull a0 = pk2(av.x, av.x);
            ull a1 = pk2(av.y, av.y);
            ull a2 = pk2(av.z, av.z);
            ull a3 = pk2(av.w, av.w);
            fma2(acc[0][0], a0, b01.x); fma2(acc[0][1], a0, b01.y);
            fma2(acc[0][2], a0, b23.x); fma2(acc[0][3], a0, b23.y);
            fma2(acc[1][0], a1, b01.x); fma2(acc[1][1], a1, b01.y);
            fma2(acc[1][2], a1, b23.x); fma2(acc[1][3], a1, b23.y);
            fma2(acc[2][0], a2, b01.x); fma2(acc[2][1], a2, b01.y);
            fma2(acc[2][2], a2, b23.x); fma2(acc[2][3], a2, b23.y);
            fma2(acc[3][0], a3, b01.x); fma2(acc[3][1], a3, b01.y);
            fma2(acc[3][2], a3, b23.x); fma2(acc[3][3], a3, b23.y);
        }
        if (s + 1 == nst) break;

        // ---- stage s+1 A (regs->smem), kick off s+2 (A regs + B cp.async) ----
        storeA((s + 1) & 1);           // buffer last read in compute(s-1): safe
        if (s + 2 < nst) {
            prefA(s + 2);
            cpB(s + 2);                // ring slot last read in compute(s-1): safe
            CP_COMMIT();
            CP_WAIT1();                // B(s+1) complete
        } else {
            CP_WAIT0();                // drain: B(s+1) complete
        }
        __syncthreads();
    }

    // ---- write partial tile ----
    const int n = n0 + tn * 8;
#pragma unroll
    for (int i = 0; i < 4; i++) {
        float2 v0 = upk(acc[i][0]), v1 = upk(acc[i][1]);
        float2 v2 = upk(acc[i][2]), v3 = upk(acc[i][3]);
        float* orow = &Out[(size_t)(b0 + tm * 4 + i) * ldO + n];
        *reinterpret_cast<float4*>(&orow[0]) = make_float4(v0.x, v0.y, v1.x, v1.y);
        *reinterpret_cast<float4*>(&orow[4]) = make_float4(v2.x, v2.y, v3.x, v3.y);
    }
}

// ---------------------------------------------------------------------------
// Per-step epilogue: sum split-K partials, time-decay decomposition,
// LSTM gate math. 65536 threads x float4.
// ---------------------------------------------------------------------------
__global__ __launch_bounds__(256) void step_epi(
    int t, const float* __restrict__ elapsed)   // [B][T]
{
    int idx = blockIdx.x * 256 + threadIdx.x;   // 0..65535
    int b = idx >> 8;
    int n4 = (idx & 255) << 2;

    const int pr = t & 1;
    const float* c_in = g_c[pr];
    float* c_out = g_c[1 - pr];
    float* h_out = g_h[1 - pr];

    float dt = elapsed[(size_t)b * T_ + t];
    float Td = 1.0f / logf(dt + 2.7183f);

    float4 dec = make_float4(0.f, 0.f, 0.f, 0.f);
    float4 gi = dec, gf = dec, go = dec, gc = dec;
#pragma unroll
    for (int s = 0; s < SK; s++) {
        float4 d = *reinterpret_cast<const float4*>(&g_decP[s][(size_t)b * H_ + n4]);
        dec.x += d.x; dec.y += d.y; dec.z += d.z; dec.w += d.w;
        const float* grow = &g_gateP[s][(size_t)b * G4];
        float4 a;
        a = *reinterpret_cast<const float4*>(&grow[0 * H_ + n4]);
        gi.x += a.x; gi.y += a.y; gi.z += a.z; gi.w += a.w;
        a = *reinterpret_cast<const float4*>(&grow[1 * H_ + n4]);
        gf.x += a.x; gf.y += a.y; gf.z += a.z; gf.w += a.w;
        a = *reinterpret_cast<const float4*>(&grow[2 * H_ + n4]);
        go.x += a.x; go.y += a.y; go.z += a.z; go.w += a.w;
        a = *reinterpret_cast<const float4*>(&grow[3 * H_ + n4]);
        gc.x += a.x; gc.y += a.y; gc.z += a.z; gc.w += a.w;
    }

    float4 bb  = *reinterpret_cast<const float4*>(&g_bd2[n4]);
    float4 cp  = *reinterpret_cast<const float4*>(&c_in[(size_t)b * H_ + n4]);
    float4 bi = *reinterpret_cast<const float4*>(&g_ball[0 * H_ + n4]);
    float4 bf = *reinterpret_cast<const float4*>(&g_ball[1 * H_ + n4]);
    float4 bo = *reinterpret_cast<const float4*>(&g_ball[2 * H_ + n4]);
    float4 bc = *reinterpret_cast<const float4*>(&g_ball[3 * H_ + n4]);

    float4 cn, hn;
#define TLSTM_COMP(X)                                                     \
    {                                                                     \
        float cst = tanhf(dec.X + bb.X);                                  \
        float cm = cp.X - cst + Td * cst;                                 \
        float c2 = sigm(gf.X + bf.X) * cm +                               \
                   sigm(gi.X + bi.X) * tanhf(gc.X + bc.X);                \
        cn.X = c2;                                                        \
        hn.X = sigm(go.X + bo.X) * tanhf(c2);                             \
    }
    TLSTM_COMP(x) TLSTM_COMP(y) TLSTM_COMP(z) TLSTM_COMP(w)
#undef TLSTM_COMP

    *reinterpret_cast<float4*>(&c_out[(size_t)b * H_ + n4]) = cn;
    *reinterpret_cast<float4*>(&h_out[(size_t)b * H_ + n4]) = hn;
}

// ---------------------------------------------------------------------------
// Output head
// ---------------------------------------------------------------------------
__global__ __launch_bounds__(256) void fc1_kernel(
    const float* __restrict__ w,     // [H][FC]
    const float* __restrict__ bias)  // [FC]
{
    int idx = blockIdx.x * 256 + threadIdx.x;  // B*FC = 131072
    int b = idx >> 9, n = idx & 511;
    const float* hrow = &g_h[0][(size_t)b * H_];
    float acc = bias[n];
#pragma unroll 8
    for (int k = 0; k < H_; k++)
        acc += hrow[k] * w[(size_t)k * FC_ + n];
    g_tmp[idx] = fmaxf(acc, 0.0f);
}

__global__ __launch_bounds__(256) void fco_kernel(
    const float* __restrict__ w,      // [FC][DOUT]
    const float* __restrict__ bias,   // [DOUT]
    float* __restrict__ out)          // [B][DOUT]
{
    int idx = blockIdx.x * 256 + threadIdx.x;  // B*DOUT = 6144
    if (idx >= B_ * DOUT) return;
    int b = idx / DOUT, n = idx % DOUT;
    const float* trow = &g_tmp[(size_t)b * FC_];
    float acc = bias[n];
#pragma unroll 8
    for (int k = 0; k < FC_; k++)
        acc += trow[k] * w[(size_t)k * DOUT + n];
    out[idx] = acc;
}

// ---------------------------------------------------------------------------
// Launch
// ---------------------------------------------------------------------------
extern "C" void kernel_launch(void* const* d_in, const int* in_sizes, int n_in,
                              void* d_out, int out_size) {
    (void)in_sizes; (void)n_in; (void)out_size;
    const float* x        = (const float*)d_in[0];
    const float* elapsed  = (const float*)d_in[1];
    const float* Wx       = (const float*)d_in[2];
    const float* Ux       = (const float*)d_in[3];
    const float* b_lin    = (const float*)d_in[4];
    const float* b_extra  = (const float*)d_in[5];
    const float* Wd       = (const float*)d_in[6];
    const float* bd       = (const float*)d_in[7];
    const float* b_decomp = (const float*)d_in[8];
    const float* fc1_w    = (const float*)d_in[9];
    const float* fc1_b    = (const float*)d_in[10];
    const float* fco_w    = (const float*)d_in[11];
    const float* fco_b    = (const float*)d_in[12];
    float* out = (float*)d_out;

    // zero initial state + prebake bias sums
    init_kernel<<<256, 256>>>(b_lin, b_extra, bd, b_decomp);

    // sequential recurrence: per step, one fused split-K GEMM + one epilogue
    for (int t = 0; t < T_; t++) {
        step_gemm<<<GTILES + DTILES, 256>>>(t, x, Ux, Wx, Wd);
        step_epi<<<256, 256>>>(t, elapsed);
    }

    // output head on final hidden state (in g_h[0] after t=255)
    fc1_kernel<<<(B_ * FC_) / 256, 256>>>(fc1_w, fc1_b);
    fco_kernel<<<(B_ * DOUT + 255) / 256, 256>>>(fco_w, fco_b, out);
}

// round 9
// speedup vs baseline: 4.0812x; 2.0274x over previous
#include <cuda_runtime.h>
#include <cuda_bf16.h>
#include <math.h>
#include <stdint.h>

typedef unsigned long long ull;

// ---------------------------------------------------------------------------
// Problem dimensions
// ---------------------------------------------------------------------------
#define B_   256
#define T_   256
#define DIN  256
#define H_   1024
#define FC_  512
#define DOUT 24
#define G4   4096
#define KTOT 1280        // H + DIN (fused [h | x_t] contraction)

// Tiling: CTA 128x128, 4 warps (2x2), warp tile 64x64, split-K = 4
#define SK 4
#define KSG (KTOT / SK)            // 320 -> 10 stages of 32
#define KSD (H_ / SK)              // 256 -> 8 stages of 32
#define NSTG (KSG / 32)
#define NSTD (KSD / 32)
#define GCTAS (2 * 32 * SK)        // 256
#define DCTAS (2 * 8 * SK)         // 64
#define NCTAS (GCTAS + DCTAS)      // 320

#define ROWB 80                    // padded row stride in bytes (40 bf16)
#define REG_BYTES 10240            // 128 rows * 80B (one of Ahi/Alo/Bhi/Blo)
#define STG_BYTES 40960            // 4 regions per stage
#define SMEM_BYTES (2 * STG_BYTES) // double buffer: 80 KB dynamic

// ---------------------------------------------------------------------------
// Device scratch (static globals — no allocation allowed)
// ---------------------------------------------------------------------------
static __device__ __align__(16) __nv_bfloat16 g_WgT0[(size_t)G4 * KTOT];  // [n][k] hi
static __device__ __align__(16) __nv_bfloat16 g_WgT1[(size_t)G4 * KTOT];  // [n][k] lo
static __device__ __align__(16) __nv_bfloat16 g_WdT0[(size_t)H_ * H_];
static __device__ __align__(16) __nv_bfloat16 g_WdT1[(size_t)H_ * H_];
static __device__ __align__(16) __nv_bfloat16 g_xs0[(size_t)B_ * T_ * DIN];
static __device__ __align__(16) __nv_bfloat16 g_xs1[(size_t)B_ * T_ * DIN];
static __device__ __align__(16) __nv_bfloat16 g_hs0[(size_t)B_ * H_];
static __device__ __align__(16) __nv_bfloat16 g_hs1[(size_t)B_ * H_];
static __device__ __align__(16) __nv_bfloat16 g_cs0[(size_t)B_ * H_];
static __device__ __align__(16) __nv_bfloat16 g_cs1[(size_t)B_ * H_];
static __device__ float g_gateP[SK][(size_t)B_ * G4];  // split-K partials
static __device__ float g_decP[SK][(size_t)B_ * H_];
static __device__ float g_hf[(size_t)B_ * H_];          // fp32 hidden (in-place)
static __device__ float g_cf[(size_t)B_ * H_];          // fp32 cell (in-place)
static __device__ float g_ball[G4];                     // b_lin + b_extra
static __device__ float g_bd2[H_];                      // bd + b_decomp
static __device__ float g_tmp[(size_t)B_ * FC_];

// ---------------------------------------------------------------------------
// Helpers (baseline PTX only — compiles under .target sm_100)
// ---------------------------------------------------------------------------
__device__ __forceinline__ uint32_t smem_u32(const void* p) {
    uint32_t a;
    asm("{ .reg .u64 t; cvta.to.shared.u64 t, %1; cvt.u32.u64 %0, t; }"
        : "=r"(a) : "l"(p));
    return a;
}
__device__ __forceinline__ void cp16(uint32_t dst, const void* src) {
    asm volatile("cp.async.cg.shared.global [%0], [%1], 16;"
                 :: "r"(dst), "l"(src));
}
#define CP_COMMIT() asm volatile("cp.async.commit_group;")
#define CP_WAIT1()  asm volatile("cp.async.wait_group 1;")
#define CP_WAIT0()  asm volatile("cp.async.wait_group 0;")

__device__ __forceinline__ void ldsm4(uint32_t* r, uint32_t addr) {
    asm volatile("ldmatrix.sync.aligned.m8n8.x4.shared.b16 {%0,%1,%2,%3}, [%4];"
                 : "=r"(r[0]), "=r"(r[1]), "=r"(r[2]), "=r"(r[3]) : "r"(addr));
}
__device__ __forceinline__ void mma16816(float* c, const uint32_t* a,
                                         uint32_t b0, uint32_t b1) {
    asm volatile(
        "mma.sync.aligned.m16n8k16.row.col.f32.bf16.bf16.f32 "
        "{%0,%1,%2,%3}, {%4,%5,%6,%7}, {%8,%9}, {%0,%1,%2,%3};"
        : "+f"(c[0]), "+f"(c[1]), "+f"(c[2]), "+f"(c[3])
        : "r"(a[0]), "r"(a[1]), "r"(a[2]), "r"(a[3]), "r"(b0), "r"(b1));
}
__device__ __forceinline__ float sigm(float x) {
    return 1.0f / (1.0f + expf(-x));
}
__device__ __forceinline__ void bsplit(float v, __nv_bfloat16& hi, __nv_bfloat16& lo) {
    hi = __float2bfloat16(v);
    lo = __float2bfloat16(v - __bfloat162float(hi));
}

// ---------------------------------------------------------------------------
// One-time prep kernels
// ---------------------------------------------------------------------------
__global__ __launch_bounds__(256) void init_state(
    const float* __restrict__ b_lin, const float* __restrict__ b_extra,
    const float* __restrict__ bd, const float* __restrict__ b_decomp)
{
    int i = blockIdx.x * 256 + threadIdx.x;           // 65536 threads
    float4 z = make_float4(0.f, 0.f, 0.f, 0.f);
    *reinterpret_cast<float4*>(&g_hf[(size_t)i * 4]) = z;
    *reinterpret_cast<float4*>(&g_cf[(size_t)i * 4]) = z;
    reinterpret_cast<ull*>(g_hs0)[i] = 0ULL;
    reinterpret_cast<ull*>(g_hs1)[i] = 0ULL;
    reinterpret_cast<ull*>(g_cs0)[i] = 0ULL;
    reinterpret_cast<ull*>(g_cs1)[i] = 0ULL;
    if (i < G4 / 4) {
        float4 a = *reinterpret_cast<const float4*>(&b_lin[i * 4]);
        float4 b = *reinterpret_cast<const float4*>(&b_extra[i * 4]);
        *reinterpret_cast<float4*>(&g_ball[i * 4]) =
            make_float4(a.x + b.x, a.y + b.y, a.z + b.z, a.w + b.w);
    }
    if (i < H_ / 4) {
        float4 a = *reinterpret_cast<const float4*>(&bd[i * 4]);
        float4 b = *reinterpret_cast<const float4*>(&b_decomp[i * 4]);
        *reinterpret_cast<float4*>(&g_bd2[i * 4]) =
            make_float4(a.x + b.x, a.y + b.y, a.z + b.z, a.w + b.w);
    }
}

// transpose [K][N] -> [N][K] with bf16 hi/lo split; gate weights (Ux ‖ Wx)
__global__ void prep_wgate(const float* __restrict__ Ux, const float* __restrict__ Wx)
{
    __shared__ float tile[32][33];
    int tx = threadIdx.x, ty = threadIdx.y;
    int k0 = blockIdx.x * 32, n0 = blockIdx.y * 32;
#pragma unroll
    for (int i = 0; i < 4; i++) {
        int k = k0 + ty + i * 8, n = n0 + tx;
        tile[ty + i * 8][tx] = (k < H_) ? Ux[(size_t)k * G4 + n]
                                        : Wx[(size_t)(k - H_) * G4 + n];
    }
    __syncthreads();
#pragma unroll
    for (int i = 0; i < 4; i++) {
        int n = n0 + ty + i * 8, k = k0 + tx;
        float v = tile[tx][ty + i * 8];
        __nv_bfloat16 hi, lo; bsplit(v, hi, lo);
        g_WgT0[(size_t)n * KTOT + k] = hi;
        g_WgT1[(size_t)n * KTOT + k] = lo;
    }
}

__global__ void prep_wd(const float* __restrict__ Wd)
{
    __shared__ float tile[32][33];
    int tx = threadIdx.x, ty = threadIdx.y;
    int k0 = blockIdx.x * 32, n0 = blockIdx.y * 32;
#pragma unroll
    for (int i = 0; i < 4; i++)
        tile[ty + i * 8][tx] = Wd[(size_t)(k0 + ty + i * 8) * H_ + n0 + tx];
    __syncthreads();
#pragma unroll
    for (int i = 0; i < 4; i++) {
        int n = n0 + ty + i * 8, k = k0 + tx;
        float v = tile[tx][ty + i * 8];
        __nv_bfloat16 hi, lo; bsplit(v, hi, lo);
        g_WdT0[(size_t)n * H_ + k] = hi;
        g_WdT1[(size_t)n * H_ + k] = lo;
    }
}

__global__ __launch_bounds__(256) void prep_x(const float* __restrict__ x)
{
    size_t i = (size_t)(blockIdx.x * 256 + threadIdx.x) * 4;
    float4 v = *reinterpret_cast<const float4*>(&x[i]);
    __nv_bfloat16 h0, l0, h1, l1, h2, l2, h3, l3;
    bsplit(v.x, h0, l0); bsplit(v.y, h1, l1);
    bsplit(v.z, h2, l2); bsplit(v.w, h3, l3);
    __nv_bfloat162 a, b;
    a.x = h0; a.y = h1; b.x = h2; b.y = h3;
    *reinterpret_cast<__nv_bfloat162*>(&g_xs0[i])     = a;
    *reinterpret_cast<__nv_bfloat162*>(&g_xs0[i + 2]) = b;
    a.x = l0; a.y = l1; b.x = l2; b.y = l3;
    *reinterpret_cast<__nv_bfloat162*>(&g_xs1[i])     = a;
    *reinterpret_cast<__nv_bfloat162*>(&g_xs1[i + 2]) = b;
}

// ---------------------------------------------------------------------------
// Per-step tensor-core GEMM via mma.sync (HMMA). 320 CTAs, 128 threads:
//   [0,256):   gates partial [128b x 128n] = [h|x_t](hi/lo) @ WgT(hi/lo)
//   [256,320): decomp partial [128b x 128n] = c(hi/lo) @ WdT(hi/lo)
// 3-term bf16 split: Ahi*Bhi + Alo*Bhi + Ahi*Blo, fp32 accumulators.
// ---------------------------------------------------------------------------
__global__ __launch_bounds__(128) void step_mma(int t)
{
    extern __shared__ __align__(16) char smem[];
    const uint32_t sbase = smem_u32(smem);

    const int bid = blockIdx.x;
    const bool isg = bid < GCTAS;

    int n0, m0, ks, nst, bstride, ldO;
    const __nv_bfloat16 *Bhi, *Blo;
    float* Out;
    if (isg) {
        int r = bid;
        ks = r & (SK - 1); r >>= 2;
        n0 = (r & 31) * 128; m0 = (r >> 5) * 128;
        nst = NSTG; bstride = KTOT; ldO = G4;
        Bhi = g_WgT0; Blo = g_WgT1; Out = &g_gateP[ks][0];
    } else {
        int r = bid - GCTAS;
        ks = r & (SK - 1); r >>= 2;
        n0 = (r & 7) * 128; m0 = (r >> 3) * 128;
        nst = NSTD; bstride = H_; ldO = H_;
        Bhi = g_WdT0; Blo = g_WdT1; Out = &g_decP[ks][0];
    }
    const int kbase = ks * (isg ? KSG : KSD);
    const __nv_bfloat16* Ahi_s = isg ? g_hs0 : g_cs0;
    const __nv_bfloat16* Alo_s = isg ? g_hs1 : g_cs1;

    const int tid  = threadIdx.x;
    const int lane = tid & 31;
    const int warp = tid >> 5;
    const int wm   = (warp >> 1) * 64;
    const int wn   = (warp & 1) * 64;

    // ldmatrix per-lane byte offsets within a region
    uint32_t aoff[4], boff[4];
#pragma unroll
    for (int mt = 0; mt < 4; mt++)
        aoff[mt] = (uint32_t)((wm + mt * 16 + (lane & 15)) * ROWB +
                              ((lane >> 4) & 1) * 16);
#pragma unroll
    for (int np = 0; np < 4; np++)
        boff[np] = (uint32_t)((wn + np * 16 + (lane & 7) + ((lane >> 4) << 3)) * ROWB +
                              ((lane >> 3) & 1) * 16);

    float acc[4][8][4];
#pragma unroll
    for (int mt = 0; mt < 4; mt++)
#pragma unroll
        for (int nt = 0; nt < 8; nt++)
#pragma unroll
            for (int q = 0; q < 4; q++) acc[mt][nt][q] = 0.f;

    // ---- cp.async stage: Ahi|Alo|Bhi|Blo, 128 rows x 32 k bf16 each ----
    auto stage = [&](int s) {
        const uint32_t sb = sbase + (uint32_t)((s & 1) * STG_BYTES);
        const int k0 = kbase + s * 32;
#pragma unroll
        for (int j = 0; j < 16; j++) {
            const int idx = j * 128 + tid;
            const int w   = idx >> 9;           // compile-time per j
            const int rem = idx & 511;
            const int rr  = rem >> 2;
            const int kc  = rem & 3;
            const int kg  = k0 + kc * 8;
            const __nv_bfloat16* src;
            if (w < 2) {
                if (isg && kg >= H_)
                    src = (w ? g_xs1 : g_xs0) +
                          ((size_t)(m0 + rr) * T_ + t) * DIN + (kg - H_);
                else
                    src = (w ? Alo_s : Ahi_s) + (size_t)(m0 + rr) * H_ + kg;
            } else {
                src = ((w == 2) ? Bhi : Blo) + (size_t)(n0 + rr) * bstride + kg;
            }
            cp16(sb + (uint32_t)(w * REG_BYTES + rr * ROWB + kc * 16), src);
        }
        CP_COMMIT();
    };

    stage(0);
    stage(1);
    CP_WAIT1();
    __syncthreads();

    for (int s = 0; ; s++) {
        const uint32_t sb = sbase + (uint32_t)((s & 1) * STG_BYTES);
#pragma unroll
        for (int kk = 0; kk < 2; kk++) {
            const uint32_t kb = sb + kk * 32;   // 16 bf16 = 32B per k16 step
            uint32_t ahif[4][4], alof[4][4], bfr[4][4];
#pragma unroll
            for (int mt = 0; mt < 4; mt++) {
                ldsm4(ahif[mt], kb + aoff[mt]);
                ldsm4(alof[mt], kb + REG_BYTES + aoff[mt]);
            }
#pragma unroll
            for (int np = 0; np < 4; np++)
                ldsm4(bfr[np], kb + 2 * REG_BYTES + boff[np]);
            // terms Ahi*Bhi and Alo*Bhi
#pragma unroll
            for (int mt = 0; mt < 4; mt++)
#pragma unroll
                for (int np = 0; np < 4; np++) {
                    mma16816(acc[mt][np * 2],     ahif[mt], bfr[np][0], bfr[np][1]);
                    mma16816(acc[mt][np * 2 + 1], ahif[mt], bfr[np][2], bfr[np][3]);
                    mma16816(acc[mt][np * 2],     alof[mt], bfr[np][0], bfr[np][1]);
                    mma16816(acc[mt][np * 2 + 1], alof[mt], bfr[np][2], bfr[np][3]);
                }
            // term Ahi*Blo (reuse bfr registers)
#pragma unroll
            for (int np = 0; np < 4; np++)
                ldsm4(bfr[np], kb + 3 * REG_BYTES + boff[np]);
#pragma unroll
            for (int mt = 0; mt < 4; mt++)
#pragma unroll
                for (int np = 0; np < 4; np++) {
                    mma16816(acc[mt][np * 2],     ahif[mt], bfr[np][0], bfr[np][1]);
                    mma16816(acc[mt][np * 2 + 1], ahif[mt], bfr[np][2], bfr[np][3]);
                }
        }
        if (s + 1 == nst) break;
        __syncthreads();                 // done reading buffer s&1
        if (s + 2 < nst) { stage(s + 2); CP_WAIT1(); }
        else             { CP_WAIT0(); }
        __syncthreads();                 // buffer (s+1)&1 fully staged
    }

    // ---- write split-K partial tile ----
    const int lr  = lane >> 2;
    const int lc2 = (lane & 3) * 2;
#pragma unroll
    for (int mt = 0; mt < 4; mt++) {
#pragma unroll
        for (int nt = 0; nt < 8; nt++) {
            const int row = m0 + wm + mt * 16 + lr;
            const int col = n0 + wn + nt * 8 + lc2;
            *reinterpret_cast<float2*>(&Out[(size_t)row * ldO + col]) =
                make_float2(acc[mt][nt][0], acc[mt][nt][1]);
            *reinterpret_cast<float2*>(&Out[(size_t)(row + 8) * ldO + col]) =
                make_float2(acc[mt][nt][2], acc[mt][nt][3]);
        }
    }
}

// ---------------------------------------------------------------------------
// Per-step epilogue: sum split-K partials, decay decomposition, LSTM gate
// math (fp32 in-place), emit bf16 hi/lo h and c for the next step.
// ---------------------------------------------------------------------------
__global__ __launch_bounds__(256) void step_epi(
    int t, const float* __restrict__ elapsed)   // [B][T]
{
    int idx = blockIdx.x * 256 + threadIdx.x;   // 0..65535
    int b = idx >> 8;
    int n4 = (idx & 255) << 2;

    float dt = elapsed[(size_t)b * T_ + t];
    float Td = 1.0f / logf(dt + 2.7183f);

    float4 dec = make_float4(0.f, 0.f, 0.f, 0.f);
    float4 gi = dec, gf = dec, go = dec, gc = dec;
#pragma unroll
    for (int s = 0; s < SK; s++) {
        float4 d = *reinterpret_cast<const float4*>(&g_decP[s][(size_t)b * H_ + n4]);
        dec.x += d.x; dec.y += d.y; dec.z += d.z; dec.w += d.w;
        const float* grow = &g_gateP[s][(size_t)b * G4];
        float4 a;
        a = *reinterpret_cast<const float4*>(&grow[0 * H_ + n4]);
        gi.x += a.x; gi.y += a.y; gi.z += a.z; gi.w += a.w;
        a = *reinterpret_cast<const float4*>(&grow[1 * H_ + n4]);
        gf.x += a.x; gf.y += a.y; gf.z += a.z; gf.w += a.w;
        a = *reinterpret_cast<const float4*>(&grow[2 * H_ + n4]);
        go.x += a.x; go.y += a.y; go.z += a.z; go.w += a.w;
        a = *reinterpret_cast<const float4*>(&grow[3 * H_ + n4]);
        gc.x += a.x; gc.y += a.y; gc.z += a.z; gc.w += a.w;
    }

    float4 bb  = *reinterpret_cast<const float4*>(&g_bd2[n4]);
    float4 cp4 = *reinterpret_cast<const float4*>(&g_cf[(size_t)b * H_ + n4]);
    float4 bi = *reinterpret_cast<const float4*>(&g_ball[0 * H_ + n4]);
    float4 bf = *reinterpret_cast<const float4*>(&g_ball[1 * H_ + n4]);
    float4 bo = *reinterpret_cast<const float4*>(&g_ball[2 * H_ + n4]);
    float4 bc = *reinterpret_cast<const float4*>(&g_ball[3 * H_ + n4]);

    float cn[4], hn[4];
#define TLSTM_COMP(K, X)                                                  \
    {                                                                     \
        float cst = tanhf(dec.X + bb.X);                                  \
        float cm = cp4.X - cst + Td * cst;                                \
        float c2 = sigm(gf.X + bf.X) * cm +                               \
                   sigm(gi.X + bi.X) * tanhf(gc.X + bc.X);                \
        cn[K] = c2;                                                       \
        hn[K] = sigm(go.X + bo.X) * tanhf(c2);                            \
    }
    TLSTM_COMP(0, x) TLSTM_COMP(1, y) TLSTM_COMP(2, z) TLSTM_COMP(3, w)
#undef TLSTM_COMP

    size_t o = (size_t)b * H_ + n4;
    *reinterpret_cast<float4*>(&g_cf[o]) = make_float4(cn[0], cn[1], cn[2], cn[3]);
    *reinterpret_cast<float4*>(&g_hf[o]) = make_float4(hn[0], hn[1], hn[2], hn[3]);

    __nv_bfloat16 chi[4], clo[4], hhi[4], hlo[4];
#pragma unroll
    for (int k = 0; k < 4; k++) {
        bsplit(cn[k], chi[k], clo[k]);
        bsplit(hn[k], hhi[k], hlo[k]);
    }
    __nv_bfloat162 p;
    p.x = chi[0]; p.y = chi[1]; *reinterpret_cast<__nv_bfloat162*>(&g_cs0[o])     = p;
    p.x = chi[2]; p.y = chi[3]; *reinterpret_cast<__nv_bfloat162*>(&g_cs0[o + 2]) = p;
    p.x = clo[0]; p.y = clo[1]; *reinterpret_cast<__nv_bfloat162*>(&g_cs1[o])     = p;
    p.x = clo[2]; p.y = clo[3]; *reinterpret_cast<__nv_bfloat162*>(&g_cs1[o + 2]) = p;
    p.x = hhi[0]; p.y = hhi[1]; *reinterpret_cast<__nv_bfloat162*>(&g_hs0[o])     = p;
    p.x = hhi[2]; p.y = hhi[3]; *reinterpret_cast<__nv_bfloat162*>(&g_hs0[o + 2]) = p;
    p.x = hlo[0]; p.y = hlo[1]; *reinterpret_cast<__nv_bfloat162*>(&g_hs1[o])     = p;
    p.x = hlo[2]; p.y = hlo[3]; *reinterpret_cast<__nv_bfloat162*>(&g_hs1[o + 2]) = p;
}

// ---------------------------------------------------------------------------
// Output head
// ---------------------------------------------------------------------------
__global__ __launch_bounds__(256) void fc1_kernel(
    const float* __restrict__ w, const float* __restrict__ bias)
{
    int idx = blockIdx.x * 256 + threadIdx.x;  // B*FC
    int b = idx >> 9, n = idx & 511;
    const float* hrow = &g_hf[(size_t)b * H_];
    float acc = bias[n];
#pragma unroll 8
    for (int k = 0; k < H_; k++)
        acc += hrow[k] * w[(size_t)k * FC_ + n];
    g_tmp[idx] = fmaxf(acc, 0.0f);
}

__global__ __launch_bounds__(256) void fco_kernel(
    const float* __restrict__ w, const float* __restrict__ bias,
    float* __restrict__ out)
{
    int idx = blockIdx.x * 256 + threadIdx.x;  // B*DOUT
    if (idx >= B_ * DOUT) return;
    int b = idx / DOUT, n = idx % DOUT;
    const float* trow = &g_tmp[(size_t)b * FC_];
    float acc = bias[n];
#pragma unroll 8
    for (int k = 0; k < FC_; k++)
        acc += trow[k] * w[(size_t)k * DOUT + n];
    out[idx] = acc;
}

// ---------------------------------------------------------------------------
// Launch
// ---------------------------------------------------------------------------
extern "C" void kernel_launch(void* const* d_in, const int* in_sizes, int n_in,
                              void* d_out, int out_size) {
    (void)in_sizes; (void)n_in; (void)out_size;
    const float* x        = (const float*)d_in[0];
    const float* elapsed  = (const float*)d_in[1];
    const float* Wx       = (const float*)d_in[2];
    const float* Ux       = (const float*)d_in[3];
    const float* b_lin    = (const float*)d_in[4];
    const float* b_extra  = (const float*)d_in[5];
    const float* Wd       = (const float*)d_in[6];
    const float* bd       = (const float*)d_in[7];
    const float* b_decomp = (const float*)d_in[8];
    const float* fc1_w    = (const float*)d_in[9];
    const float* fc1_b    = (const float*)d_in[10];
    const float* fco_w    = (const float*)d_in[11];
    const float* fco_b    = (const float*)d_in[12];
    float* out = (float*)d_out;

    static int smem_set = 0;
    if (!smem_set) {
        cudaFuncSetAttribute(step_mma,
                             cudaFuncAttributeMaxDynamicSharedMemorySize,
                             SMEM_BYTES);
        smem_set = 1;
    }

    // one-time prep (inside graph; deterministic per call)
    init_state<<<256, 256>>>(b_lin, b_extra, bd, b_decomp);
    prep_wgate<<<dim3(KTOT / 32, G4 / 32), dim3(32, 8)>>>(Ux, Wx);
    prep_wd<<<dim3(H_ / 32, H_ / 32), dim3(32, 8)>>>(Wd);
    prep_x<<<(B_ * T_ * DIN / 4) / 256, 256>>>(x);

    // sequential recurrence: HMMA GEMM + elementwise epilogue per step
    for (int t = 0; t < T_; t++) {
        step_mma<<<NCTAS, 128, SMEM_BYTES>>>(t);
        step_epi<<<256, 256>>>(t, elapsed);
    }

    fc1_kernel<<<(B_ * FC_) / 256, 256>>>(fc1_w, fc1_b);
    fco_kernel<<<(B_ * DOUT + 255) / 256, 256>>>(fco_w, fco_b, out);
}